// round 1
// baseline (speedup 1.0000x reference)
#include <cuda_runtime.h>
#include <cstddef>

// Problem constants
#define BB   4
#define SS   1024
#define EE   1024
#define HH   16
#define DD   64
#define LD3E 3072            // 3*E

// Scratch (device globals -- no cudaMalloc allowed)
__device__ float g_qkv[BB * SS * LD3E];          // 48 MB  (B,S,3E)
__device__ float g_P[BB * HH * SS * SS];         // 256 MB (B*H, S, S)
__device__ float g_attn[BB * SS * EE];           // 16 MB  (B,S,E)

// ---------------------------------------------------------------------------
// Generic tiled GEMM: C[m,n] = sum_k A[m,k]*B[k,n] (+ bias[n])
// 64x64 tile, BK=16, 256 threads, 4x4 per thread.
// ---------------------------------------------------------------------------
__global__ void __launch_bounds__(256) gemm_nn_bias(
    const float* __restrict__ A, const float* __restrict__ B,
    const float* __restrict__ bias, float* __restrict__ C,
    int K, int lda, int ldb, int ldc)
{
    __shared__ float As[16][65];   // As[k][m], pad 65: conflict-free STS/LDS
    __shared__ float Bs[16][68];   // Bs[k][n], pad 68: 16B-aligned rows for LDS.128
    const int t  = threadIdx.x;
    const int tx = t & 15, ty = t >> 4;
    const int m0 = blockIdx.y * 64, n0 = blockIdx.x * 64;

    float acc[4][4] = {};
    for (int k0 = 0; k0 < K; k0 += 16) {
        #pragma unroll
        for (int i = 0; i < 4; i++) {
            int idx = t + i * 256;
            int m = idx >> 4, kk = idx & 15;
            As[kk][m] = A[(size_t)(m0 + m) * lda + k0 + kk];
            int kb = idx >> 6, n = idx & 63;
            Bs[kb][n] = B[(size_t)(k0 + kb) * ldb + n0 + n];
        }
        __syncthreads();
        #pragma unroll
        for (int kk = 0; kk < 16; kk++) {
            float4 bv = *(const float4*)&Bs[kk][tx * 4];
            float a[4];
            #pragma unroll
            for (int i = 0; i < 4; i++) a[i] = As[kk][ty * 4 + i];
            float bb[4] = {bv.x, bv.y, bv.z, bv.w};
            #pragma unroll
            for (int i = 0; i < 4; i++)
                #pragma unroll
                for (int j = 0; j < 4; j++)
                    acc[i][j] += a[i] * bb[j];
        }
        __syncthreads();
    }
    #pragma unroll
    for (int i = 0; i < 4; i++) {
        int m = m0 + ty * 4 + i;
        int n = n0 + tx * 4;
        float4 o = make_float4(acc[i][0], acc[i][1], acc[i][2], acc[i][3]);
        if (bias) { o.x += bias[n]; o.y += bias[n+1]; o.z += bias[n+2]; o.w += bias[n+3]; }
        *(float4*)&C[(size_t)m * ldc + n] = o;
    }
}

// ---------------------------------------------------------------------------
// K2: scores.  P[bh, x, y] = scale * sum_d Q[x,d] * K[y,d]  (batched NT GEMM)
// Full K=64 tile in smem.
// ---------------------------------------------------------------------------
__global__ void __launch_bounds__(256) scores_kernel(
    const float* __restrict__ qkv, float* __restrict__ P, float scale)
{
    __shared__ float As[64][65];   // As[d][m]
    __shared__ float Bs[64][68];   // Bs[d][n]
    const int t  = threadIdx.x;
    const int tx = t & 15, ty = t >> 4;
    const int bh = blockIdx.z, b = bh >> 4, h = bh & 15;
    const int m0 = blockIdx.y * 64, n0 = blockIdx.x * 64;

    const float* Q  = qkv + (size_t)b * SS * LD3E + h * DD;        // Q[s*LD3E + d]
    const float* Km = Q + EE;                                       // K at +E
    float* Cp = P + (size_t)bh * SS * SS;

    #pragma unroll
    for (int i = 0; i < 16; i++) {
        int idx = t + i * 256;
        int r = idx >> 6, c = idx & 63;        // 64 rows x 64 d, d contiguous
        As[c][r] = Q [(size_t)(m0 + r) * LD3E + c];
        Bs[c][r] = Km[(size_t)(n0 + r) * LD3E + c];
    }
    __syncthreads();

    float acc[4][4] = {};
    #pragma unroll 16
    for (int k = 0; k < 64; k++) {
        float4 bv = *(const float4*)&Bs[k][tx * 4];
        float a[4];
        #pragma unroll
        for (int i = 0; i < 4; i++) a[i] = As[k][ty * 4 + i];
        float bb[4] = {bv.x, bv.y, bv.z, bv.w};
        #pragma unroll
        for (int i = 0; i < 4; i++)
            #pragma unroll
            for (int j = 0; j < 4; j++)
                acc[i][j] += a[i] * bb[j];
    }
    #pragma unroll
    for (int i = 0; i < 4; i++) {
        float4 o = make_float4(scale * acc[i][0], scale * acc[i][1],
                               scale * acc[i][2], scale * acc[i][3]);
        *(float4*)&Cp[(size_t)(m0 + ty * 4 + i) * SS + n0 + tx * 4] = o;
    }
}

// ---------------------------------------------------------------------------
// K3: relative position bias.
// P[bh, x, y] += scale * sum_c q[bh, x, c] * pe[x, y, c]
// One block per (x, y-tile): a (64bh x 64y x 64c) GEMM. pe streamed once.
// ---------------------------------------------------------------------------
__global__ void __launch_bounds__(256) pe_add_kernel(
    const float* __restrict__ qkv, const float* __restrict__ pe,
    float* __restrict__ P, float scale)
{
    __shared__ float As[64][65];   // As[c][bh]
    __shared__ float Bs[64][68];   // Bs[c][y]
    const int t  = threadIdx.x;
    const int tx = t & 15, ty = t >> 4;
    const int x  = blockIdx.y;
    const int y0 = blockIdx.x * 64;

    #pragma unroll
    for (int i = 0; i < 16; i++) {
        int idx = t + i * 256;
        int r = idx >> 6, c = idx & 63;
        int b = r >> 4, h = r & 15;
        As[c][r] = qkv[(size_t)(b * SS + x) * LD3E + h * DD + c];
        Bs[c][r] = pe [((size_t)x * SS + (y0 + r)) * DD + c];
    }
    __syncthreads();

    float acc[4][4] = {};
    #pragma unroll 16
    for (int k = 0; k < 64; k++) {
        float4 bv = *(const float4*)&Bs[k][tx * 4];
        float a[4];
        #pragma unroll
        for (int i = 0; i < 4; i++) a[i] = As[k][ty * 4 + i];
        float bb[4] = {bv.x, bv.y, bv.z, bv.w};
        #pragma unroll
        for (int i = 0; i < 4; i++)
            #pragma unroll
            for (int j = 0; j < 4; j++)
                acc[i][j] += a[i] * bb[j];
    }
    #pragma unroll
    for (int i = 0; i < 4; i++) {
        int bh = ty * 4 + i;
        float* cp = &P[((size_t)bh * SS + x) * SS + y0 + tx * 4];
        float4 o = *(const float4*)cp;
        o.x += scale * acc[i][0];
        o.y += scale * acc[i][1];
        o.z += scale * acc[i][2];
        o.w += scale * acc[i][3];
        *(float4*)cp = o;
    }
}

// ---------------------------------------------------------------------------
// K4: attn[b, x, h*D + d] = sum_y P[bh, x, y] * V[y, d]   (batched, N=64)
// ---------------------------------------------------------------------------
__global__ void __launch_bounds__(256) attn_pv_kernel(
    const float* __restrict__ P, const float* __restrict__ qkv,
    float* __restrict__ attn)
{
    __shared__ float As[16][65];
    __shared__ float Bs[16][68];
    const int t  = threadIdx.x;
    const int tx = t & 15, ty = t >> 4;
    const int bh = blockIdx.z, b = bh >> 4, h = bh & 15;
    const int m0 = blockIdx.y * 64;

    const float* A = P + (size_t)bh * SS * SS;
    const float* V = qkv + (size_t)b * SS * LD3E + 2 * EE + h * DD;

    float acc[4][4] = {};
    for (int k0 = 0; k0 < SS; k0 += 16) {
        #pragma unroll
        for (int i = 0; i < 4; i++) {
            int idx = t + i * 256;
            int m = idx >> 4, kk = idx & 15;
            As[kk][m] = A[(size_t)(m0 + m) * SS + k0 + kk];
            int kb = idx >> 6, n = idx & 63;
            Bs[kb][n] = V[(size_t)(k0 + kb) * LD3E + n];
        }
        __syncthreads();
        #pragma unroll
        for (int kk = 0; kk < 16; kk++) {
            float4 bv = *(const float4*)&Bs[kk][tx * 4];
            float a[4];
            #pragma unroll
            for (int i = 0; i < 4; i++) a[i] = As[kk][ty * 4 + i];
            float bb[4] = {bv.x, bv.y, bv.z, bv.w};
            #pragma unroll
            for (int i = 0; i < 4; i++)
                #pragma unroll
                for (int j = 0; j < 4; j++)
                    acc[i][j] += a[i] * bb[j];
        }
        __syncthreads();
    }
    #pragma unroll
    for (int i = 0; i < 4; i++) {
        int m = m0 + ty * 4 + i;
        float4 o = make_float4(acc[i][0], acc[i][1], acc[i][2], acc[i][3]);
        *(float4*)&attn[((size_t)(b * SS + m)) * EE + h * DD + tx * 4] = o;
    }
}

// ---------------------------------------------------------------------------
// Launch: 5 kernels on the default stream, graph-capturable, no allocations.
// Input order (metadata): x, W_qkv, b_qkv, pe, W_out, b_out
// ---------------------------------------------------------------------------
extern "C" void kernel_launch(void* const* d_in, const int* in_sizes, int n_in,
                              void* d_out, int out_size)
{
    const float* x     = (const float*)d_in[0];
    const float* W_qkv = (const float*)d_in[1];
    const float* b_qkv = (const float*)d_in[2];
    const float* pe    = (const float*)d_in[3];
    const float* W_out = (const float*)d_in[4];
    const float* b_out = (const float*)d_in[5];
    float* out = (float*)d_out;

    float *qkv_p, *P_p, *attn_p;
    cudaGetSymbolAddress((void**)&qkv_p,  g_qkv);
    cudaGetSymbolAddress((void**)&P_p,    g_P);
    cudaGetSymbolAddress((void**)&attn_p, g_attn);

    const float scale = 0.125f;   // D^-0.5, D=64
    dim3 blk(256);

    // K1: qkv = x @ W_qkv + b_qkv        (4096 x 3072 x 1024)
    gemm_nn_bias<<<dim3(LD3E / 64, (BB * SS) / 64), blk>>>(
        x, W_qkv, b_qkv, qkv_p, EE, EE, LD3E, LD3E);

    // K2: P = scale * Q K^T per (b,h)    (64 x 1024 x 1024 x 64)
    scores_kernel<<<dim3(SS / 64, SS / 64, BB * HH), blk>>>(qkv_p, P_p, scale);

    // K3: P += scale * q_x . pe[x]       (1024 x-slices, pe streamed once)
    pe_add_kernel<<<dim3(SS / 64, SS), blk>>>(qkv_p, pe, P_p, scale);

    // K4: attn = P @ V per (b,h)         (64 x 1024 x 64 x 1024)
    attn_pv_kernel<<<dim3(1, SS / 64, BB * HH), blk>>>(P_p, qkv_p, attn_p);

    // K5: out = attn @ W_out + b_out     (4096 x 1024 x 1024)
    gemm_nn_bias<<<dim3(EE / 64, (BB * SS) / 64), blk>>>(
        attn_p, W_out, b_out, out, EE, EE, EE, EE);
}

// round 2
// speedup vs baseline: 1.1652x; 1.1652x over previous
#include <cuda_runtime.h>
#include <cstddef>

#define BB   4
#define SS   1024
#define EE   1024
#define HH   16
#define DD   64
#define LD3E 3072

__device__ float g_qkv[BB * SS * LD3E];          // 48 MB
__device__ float g_P[BB * HH * SS * SS];         // 256 MB
__device__ float g_attn[BB * SS * EE];           // 16 MB

// ---------------------------------------------------------------------------
// 8x8 packed-f32x2 microkernel: acc[i][j] (j = n-pair) += a[i] * b2[j]
// ---------------------------------------------------------------------------
__device__ __forceinline__ void mk8x8(unsigned long long (&acc)[8][4],
                                      const float* __restrict__ arow,
                                      const float* __restrict__ brow)
{
    float4 av0 = *(const float4*)(arow);
    float4 av1 = *(const float4*)(arow + 4);
    ulonglong2 bv0 = *(const ulonglong2*)(brow);
    ulonglong2 bv1 = *(const ulonglong2*)(brow + 4);
    unsigned long long b2[4] = {bv0.x, bv0.y, bv1.x, bv1.y};
    float a[8] = {av0.x, av0.y, av0.z, av0.w, av1.x, av1.y, av1.z, av1.w};
    #pragma unroll
    for (int i = 0; i < 8; i++) {
        unsigned long long a2;
        unsigned int au = __float_as_uint(a[i]);
        asm("mov.b64 %0, {%1, %1};" : "=l"(a2) : "r"(au));
        #pragma unroll
        for (int j = 0; j < 4; j++)
            asm("fma.rn.f32x2 %0, %1, %2, %0;" : "+l"(acc[i][j]) : "l"(a2), "l"(b2[j]));
    }
}

__device__ __forceinline__ float2 lo2(unsigned long long v) { return *(float2*)&v; }

// ---------------------------------------------------------------------------
// K1/K5: C = A(m,k) @ B(k,n) + bias.  128x128 tile, BK=16, 256 threads.
// ---------------------------------------------------------------------------
__global__ void __launch_bounds__(256) gemm_nn_f2(
    const float* __restrict__ A, const float* __restrict__ B,
    const float* __restrict__ bias, float* __restrict__ C,
    int K, int lda, int ldb, int ldc)
{
    __shared__ __align__(16) float As[16][132];
    __shared__ __align__(16) float Bs[16][132];
    const int t  = threadIdx.x;
    const int tx = t & 15, ty = t >> 4;
    const int m0 = blockIdx.y * 128, n0 = blockIdx.x * 128;

    const int lm = t >> 2, lkq = (t & 3) * 4;      // A loader: row lm/lm+64, k quad
    const int ln = (t & 31) * 4, lkr = t >> 5;     // B loader: n quad, k row lkr/lkr+8

    unsigned long long acc[8][4] = {};
    for (int k0 = 0; k0 < K; k0 += 16) {
        #pragma unroll
        for (int r = 0; r < 2; r++) {
            float4 va = *(const float4*)&A[(size_t)(m0 + lm + r * 64) * lda + k0 + lkq];
            As[lkq + 0][lm + r * 64] = va.x;
            As[lkq + 1][lm + r * 64] = va.y;
            As[lkq + 2][lm + r * 64] = va.z;
            As[lkq + 3][lm + r * 64] = va.w;
            float4 vb = *(const float4*)&B[(size_t)(k0 + lkr + r * 8) * ldb + n0 + ln];
            *(float4*)&Bs[lkr + r * 8][ln] = vb;
        }
        __syncthreads();
        #pragma unroll
        for (int kk = 0; kk < 16; kk++)
            mk8x8(acc, &As[kk][ty * 8], &Bs[kk][tx * 8]);
        __syncthreads();
    }
    #pragma unroll
    for (int i = 0; i < 8; i++) {
        int m = m0 + ty * 8 + i, n = n0 + tx * 8;
        float2 p0 = lo2(acc[i][0]), p1 = lo2(acc[i][1]);
        float2 p2 = lo2(acc[i][2]), p3 = lo2(acc[i][3]);
        float4 o0 = make_float4(p0.x, p0.y, p1.x, p1.y);
        float4 o1 = make_float4(p2.x, p2.y, p3.x, p3.y);
        o0.x += bias[n];     o0.y += bias[n + 1];
        o0.z += bias[n + 2]; o0.w += bias[n + 3];
        o1.x += bias[n + 4]; o1.y += bias[n + 5];
        o1.z += bias[n + 6]; o1.w += bias[n + 7];
        *(float4*)&C[(size_t)m * ldc + n]     = o0;
        *(float4*)&C[(size_t)m * ldc + n + 4] = o1;
    }
}

// ---------------------------------------------------------------------------
// K2: P[bh,x,y] = scale * sum_d Q[x,d] K[y,d].  128x128 tile, K=64.
// ---------------------------------------------------------------------------
__global__ void __launch_bounds__(256) scores_f2(
    const float* __restrict__ qkv, float* __restrict__ P, float scale)
{
    __shared__ __align__(16) float As[16][132];
    __shared__ __align__(16) float Bs[16][132];
    const int t  = threadIdx.x;
    const int tx = t & 15, ty = t >> 4;
    const int bh = blockIdx.z, b = bh >> 4, h = bh & 15;
    const int m0 = blockIdx.y * 128, n0 = blockIdx.x * 128;

    const float* Q  = qkv + (size_t)b * SS * LD3E + h * DD;
    const float* Km = Q + EE;
    float* Cp = P + (size_t)bh * SS * SS;

    const int lm = t >> 2, lkq = (t & 3) * 4;

    unsigned long long acc[8][4] = {};
    for (int k0 = 0; k0 < DD; k0 += 16) {
        #pragma unroll
        for (int r = 0; r < 2; r++) {
            float4 va = *(const float4*)&Q [(size_t)(m0 + lm + r * 64) * LD3E + k0 + lkq];
            float4 vb = *(const float4*)&Km[(size_t)(n0 + lm + r * 64) * LD3E + k0 + lkq];
            As[lkq + 0][lm + r * 64] = va.x;
            As[lkq + 1][lm + r * 64] = va.y;
            As[lkq + 2][lm + r * 64] = va.z;
            As[lkq + 3][lm + r * 64] = va.w;
            Bs[lkq + 0][lm + r * 64] = vb.x;
            Bs[lkq + 1][lm + r * 64] = vb.y;
            Bs[lkq + 2][lm + r * 64] = vb.z;
            Bs[lkq + 3][lm + r * 64] = vb.w;
        }
        __syncthreads();
        #pragma unroll
        for (int kk = 0; kk < 16; kk++)
            mk8x8(acc, &As[kk][ty * 8], &Bs[kk][tx * 8]);
        __syncthreads();
    }
    #pragma unroll
    for (int i = 0; i < 8; i++) {
        int m = m0 + ty * 8 + i, n = n0 + tx * 8;
        float2 p0 = lo2(acc[i][0]), p1 = lo2(acc[i][1]);
        float2 p2 = lo2(acc[i][2]), p3 = lo2(acc[i][3]);
        float4 o0 = make_float4(scale*p0.x, scale*p0.y, scale*p1.x, scale*p1.y);
        float4 o1 = make_float4(scale*p2.x, scale*p2.y, scale*p3.x, scale*p3.y);
        *(float4*)&Cp[(size_t)m * SS + n]     = o0;
        *(float4*)&Cp[(size_t)m * SS + n + 4] = o1;
    }
}

// ---------------------------------------------------------------------------
// K3: P[bh,x,y] += scale * sum_c q[bh,x,c] pe[x,y,c].  64(bh) x 128(y), K=64.
// 128 threads (tx 0..15, ty 0..7).
// ---------------------------------------------------------------------------
__global__ void __launch_bounds__(128) pe_add_f2(
    const float* __restrict__ qkv, const float* __restrict__ pe,
    float* __restrict__ P, float scale)
{
    __shared__ __align__(16) float As[16][68];
    __shared__ __align__(16) float Bs[16][132];
    const int t  = threadIdx.x;
    const int tx = t & 15, ty = t >> 4;
    const int x  = blockIdx.y;
    const int y0 = blockIdx.x * 128;

    const int lr = t >> 2, lkq = (t & 3) * 4;

    unsigned long long acc[8][4] = {};
    for (int k0 = 0; k0 < DD; k0 += 16) {
        // A: q rows = bh (64), k-contiguous
        #pragma unroll
        for (int r = 0; r < 2; r++) {
            int bhh = lr + r * 32, b = bhh >> 4, h = bhh & 15;
            float4 va = *(const float4*)&qkv[(size_t)(b * SS + x) * LD3E + h * DD + k0 + lkq];
            As[lkq + 0][bhh] = va.x;
            As[lkq + 1][bhh] = va.y;
            As[lkq + 2][bhh] = va.z;
            As[lkq + 3][bhh] = va.w;
        }
        // B: pe rows = y (128), c-contiguous
        #pragma unroll
        for (int r = 0; r < 4; r++) {
            int y = lr + r * 32;
            float4 vb = *(const float4*)&pe[((size_t)x * SS + y0 + y) * DD + k0 + lkq];
            Bs[lkq + 0][y] = vb.x;
            Bs[lkq + 1][y] = vb.y;
            Bs[lkq + 2][y] = vb.z;
            Bs[lkq + 3][y] = vb.w;
        }
        __syncthreads();
        #pragma unroll
        for (int kk = 0; kk < 16; kk++)
            mk8x8(acc, &As[kk][ty * 8], &Bs[kk][tx * 8]);
        __syncthreads();
    }
    #pragma unroll
    for (int i = 0; i < 8; i++) {
        int bhh = ty * 8 + i, n = y0 + tx * 8;
        float* cp = &P[((size_t)bhh * SS + x) * SS + n];
        float2 p0 = lo2(acc[i][0]), p1 = lo2(acc[i][1]);
        float2 p2 = lo2(acc[i][2]), p3 = lo2(acc[i][3]);
        float4 o0 = *(const float4*)cp;
        float4 o1 = *(const float4*)(cp + 4);
        o0.x += scale * p0.x; o0.y += scale * p0.y;
        o0.z += scale * p1.x; o0.w += scale * p1.y;
        o1.x += scale * p2.x; o1.y += scale * p2.y;
        o1.z += scale * p3.x; o1.w += scale * p3.y;
        *(float4*)cp       = o0;
        *(float4*)(cp + 4) = o1;
    }
}

// ---------------------------------------------------------------------------
// K4: attn = P @ V per bh.  128(x) x 64(d), K=1024.  128 threads (tx 0..7, ty 0..15).
// ---------------------------------------------------------------------------
__global__ void __launch_bounds__(128) attn_pv_f2(
    const float* __restrict__ P, const float* __restrict__ qkv,
    float* __restrict__ attn)
{
    __shared__ __align__(16) float As[16][132];
    __shared__ __align__(16) float Bs[16][68];
    const int t  = threadIdx.x;
    const int tx = t & 7, ty = t >> 3;
    const int bh = blockIdx.y, b = bh >> 4, h = bh & 15;
    const int m0 = blockIdx.x * 128;

    const float* Ap = P + (size_t)bh * SS * SS;
    const float* V  = qkv + (size_t)b * SS * LD3E + 2 * EE + h * DD;

    const int lm = t >> 2, lkq = (t & 3) * 4;      // A transpose loader
    const int ln = (t & 15) * 4, lkr = t >> 4;     // B direct loader

    unsigned long long acc[8][4] = {};
    for (int k0 = 0; k0 < SS; k0 += 16) {
        #pragma unroll
        for (int r = 0; r < 4; r++) {
            int m = lm + r * 32;
            float4 va = *(const float4*)&Ap[(size_t)(m0 + m) * SS + k0 + lkq];
            As[lkq + 0][m] = va.x;
            As[lkq + 1][m] = va.y;
            As[lkq + 2][m] = va.z;
            As[lkq + 3][m] = va.w;
        }
        #pragma unroll
        for (int r = 0; r < 2; r++) {
            float4 vb = *(const float4*)&V[(size_t)(k0 + lkr + r * 8) * LD3E + ln];
            *(float4*)&Bs[lkr + r * 8][ln] = vb;
        }
        __syncthreads();
        #pragma unroll
        for (int kk = 0; kk < 16; kk++)
            mk8x8(acc, &As[kk][ty * 8], &Bs[kk][tx * 8]);
        __syncthreads();
    }
    #pragma unroll
    for (int i = 0; i < 8; i++) {
        int m = m0 + ty * 8 + i, n = tx * 8;
        float2 p0 = lo2(acc[i][0]), p1 = lo2(acc[i][1]);
        float2 p2 = lo2(acc[i][2]), p3 = lo2(acc[i][3]);
        float4 o0 = make_float4(p0.x, p0.y, p1.x, p1.y);
        float4 o1 = make_float4(p2.x, p2.y, p3.x, p3.y);
        float* op = &attn[((size_t)(b * SS + m)) * EE + h * DD + n];
        *(float4*)op       = o0;
        *(float4*)(op + 4) = o1;
    }
}

// ---------------------------------------------------------------------------
extern "C" void kernel_launch(void* const* d_in, const int* in_sizes, int n_in,
                              void* d_out, int out_size)
{
    const float* x     = (const float*)d_in[0];
    const float* W_qkv = (const float*)d_in[1];
    const float* b_qkv = (const float*)d_in[2];
    const float* pe    = (const float*)d_in[3];
    const float* W_out = (const float*)d_in[4];
    const float* b_out = (const float*)d_in[5];
    float* out = (float*)d_out;

    float *qkv_p, *P_p, *attn_p;
    cudaGetSymbolAddress((void**)&qkv_p,  g_qkv);
    cudaGetSymbolAddress((void**)&P_p,    g_P);
    cudaGetSymbolAddress((void**)&attn_p, g_attn);

    const float scale = 0.125f;

    // K1: qkv = x @ W_qkv + b_qkv   (4096 x 3072 x 1024)
    gemm_nn_f2<<<dim3(LD3E / 128, (BB * SS) / 128), 256>>>(
        x, W_qkv, b_qkv, qkv_p, EE, EE, LD3E, LD3E);

    // K2: P = scale * Q K^T per bh
    scores_f2<<<dim3(SS / 128, SS / 128, BB * HH), 256>>>(qkv_p, P_p, scale);

    // K3: P += scale * q . pe[x]
    pe_add_f2<<<dim3(SS / 128, SS), 128>>>(qkv_p, pe, P_p, scale);

    // K4: attn = P @ V per bh
    attn_pv_f2<<<dim3(SS / 128, BB * HH), 128>>>(P_p, qkv_p, attn_p);

    // K5: out = attn @ W_out + b_out  (4096 x 1024 x 1024)
    gemm_nn_f2<<<dim3(EE / 128, (BB * SS) / 128), 256>>>(
        attn_p, W_out, b_out, out, EE, EE, EE, EE);
}